// round 10
// baseline (speedup 1.0000x reference)
#include <cuda_runtime.h>
#include <cuda_fp16.h>
#include <cstdint>

#define H   2048
#define I   1408
#define E   8
#define T   512
#define I2  2816   // 2*I
#define IW  704    // I/2: act row width in uint32 (fp16 pairs)
#define HW  1024   // H/2: x row width in uint32 (fp16 pairs)

// per-CTA dynamic smem: A fp16 ring 3x4KB @0, B fp16 double 2x8KB @0x3000
#define A_STG(k) ((((k) % 3)) << 12)
#define B_BUF(b) (0x3000 + ((b) << 13))
#define SMEM1    0x8400   // gemm1: epilogue stage 64*132*4 = 33792
#define SMEM2    0x7000   // gemm2: rings only (28KB)

// ---------------- device scratch (no allocations allowed) ----------------
__device__ int   g_cnt[E];
__device__ int   g_tok[E][T];
__device__ float g_cw [E][T];
__device__ __align__(16) uint32_t g_act[(size_t)E * T * IW];  // fp16 pairs
__device__ __align__(16) uint32_t g_x  [(size_t)T * HW];      // fp16 pairs

// ---------------- helpers ----------------
__device__ __forceinline__ uint32_t smem_u32(const void* p) {
    uint32_t a;
    asm("{ .reg .u64 t; cvta.to.shared.u64 t, %1; cvt.u32.u64 %0, t; }" : "=r"(a) : "l"(p));
    return a;
}
// pack two fp32 -> fp16x2 (first arg in low 16 bits)
__device__ __forceinline__ uint32_t packh(float lo, float hi) {
    uint32_t r;
    asm("cvt.rn.f16x2.f32 %0, %1, %2;" : "=r"(r) : "f"(hi), "f"(lo));
    return r;
}
__device__ __forceinline__ void ldsm4(uint32_t* r, uint32_t a) {
    asm volatile("ldmatrix.sync.aligned.m8n8.x4.shared.b16 {%0,%1,%2,%3}, [%4];"
        : "=r"(r[0]), "=r"(r[1]), "=r"(r[2]), "=r"(r[3]) : "r"(a));
}
__device__ __forceinline__ void mma_h(float* d, const uint32_t* a, uint32_t b0, uint32_t b1) {
    asm volatile("mma.sync.aligned.m16n8k16.row.col.f32.f16.f16.f32 "
        "{%0,%1,%2,%3}, {%4,%5,%6,%7}, {%8,%9}, {%0,%1,%2,%3};"
        : "+f"(d[0]), "+f"(d[1]), "+f"(d[2]), "+f"(d[3])
        : "r"(a[0]), "r"(a[1]), "r"(a[2]), "r"(a[3]), "r"(b0), "r"(b1));
}
#define CP16(d_, s_)  asm volatile("cp.async.cg.shared.global [%0], [%1], 16;" :: "r"(d_), "l"(s_))
#define CPCOMMIT()    asm volatile("cp.async.commit_group;" ::)
#define CPWAIT(n_)    asm volatile("cp.async.wait_group %0;" :: "n"(n_))

// ---------------- init ----------------
__global__ void k_init() {
    if (threadIdx.x < E) g_cnt[threadIdx.x] = 0;
}

// ---------------- router: zero out row, convert x row to fp16, route ----------------
__global__ void k_router(const float* __restrict__ x, const float* __restrict__ wg,
                         float* __restrict__ out) {
    const int t = blockIdx.x, tid = threadIdx.x, w = tid >> 5, lane = tid & 31;
    const float* xr = x + (size_t)t * H;
    float4 z = make_float4(0.f, 0.f, 0.f, 0.f);
    *(float4*)(out + (size_t)t * H + tid * 4)        = z;
    *(float4*)(out + (size_t)t * H + 1024 + tid * 4) = z;
    #pragma unroll
    for (int i = tid * 4; i < H; i += 1024) {
        float4 v = *(const float4*)(xr + i);
        *(uint2*)(g_x + (size_t)t * HW + i / 2) =
            make_uint2(packh(v.x, v.y), packh(v.z, v.w));
    }
    const float* gr = wg + (size_t)w * H;
    float s = 0.f;
    for (int i = lane * 4; i < H; i += 128) {
        float4 xv = *(const float4*)(xr + i);
        float4 gv = *(const float4*)(gr + i);
        s += xv.x * gv.x + xv.y * gv.y + xv.z * gv.z + xv.w * gv.w;
    }
    #pragma unroll
    for (int o = 16; o; o >>= 1) s += __shfl_xor_sync(0xffffffffu, s, o);
    __shared__ float lg[E];
    if (lane == 0) lg[w] = s;
    __syncthreads();
    if (tid == 0) {
        float mx = lg[0];
        #pragma unroll
        for (int e = 1; e < E; e++) mx = fmaxf(mx, lg[e]);
        float ex[E];
        #pragma unroll
        for (int e = 0; e < E; e++) ex[e] = expf(lg[e] - mx);
        int i0 = 0;
        #pragma unroll
        for (int e = 1; e < E; e++) if (ex[e] > ex[i0]) i0 = e;
        int i1 = (i0 == 0) ? 1 : 0;
        #pragma unroll
        for (int e = 0; e < E; e++) if (e != i0 && ex[e] > ex[i1]) i1 = e;
        float s0 = ex[i0], s1 = ex[i1], inv = 1.f / (s0 + s1);
        int p0 = atomicAdd(&g_cnt[i0], 1);
        g_tok[i0][p0] = t;  g_cw[i0][p0] = s0 * inv;
        int p1 = atomicAdd(&g_cnt[i1], 1);
        g_tok[i1][p1] = t;  g_cw[i1][p1] = s1 * inv;
    }
}

// A cp.async: 2 thr/row, 32B each (two 16B chunks)
#define ISSUE_A(kt_)                                                            \
    do {                                                                        \
        if ((kt_) < KT) {                                                       \
            uint32_t st = sbase + A_STG(kt_);                                   \
            const uint32_t* s = arow + (kt_) * 16 + q * 8;                      \
            CP16(st + a_d0, (const char*)s);                                    \
            CP16(st + a_d1, (const char*)(s + 4));                              \
        }                                                                       \
        CPCOMMIT();                                                             \
    } while (0)

// B: 1 thr/row, 128B fp32 per row-kt in two 64B half-rounds (bv reused)
#define LDG_BH(kt_, hh_)                                                        \
    { const float* p = bptr + (size_t)(kt_) * 32 + (hh_) * 16;                  \
      bv[0] = *(const float4*)p;       bv[1] = *(const float4*)(p + 4);         \
      bv[2] = *(const float4*)(p + 8); bv[3] = *(const float4*)(p + 12); }

#define STS_BH(b_, hh_)                                                         \
    { char* s = sm + B_BUF(b_);                                                 \
      uint32_t u[8];                                                            \
      _Pragma("unroll")                                                         \
      for (int i = 0; i < 4; i++) {                                             \
          u[2*i]   = packh(bv[i].x, bv[i].y);                                   \
          u[2*i+1] = packh(bv[i].z, bv[i].w);                                   \
      }                                                                         \
      *(uint4*)(s + b_base + ((((hh_) * 32))      ^ b_sw)) = make_uint4(u[0], u[1], u[2], u[3]); \
      *(uint4*)(s + b_base + ((((hh_) * 32) + 16) ^ b_sw)) = make_uint4(u[4], u[5], u[6], u[7]); \
    }

// one kk phase of the 32m x 64n warp tile (2 A ldsm4, 4 B ldsm4, 16 mma)
#define COMPUTE_KK(kk_, aoff_, boff_)                                           \
    {                                                                           \
        uint32_t Ah[2][4], Bh[4][4];                                            \
        _Pragma("unroll")                                                       \
        for (int mt = 0; mt < 2; mt++)                                          \
            ldsm4(Ah[mt], (aoff_) + ((a_swb + mt * 1024) ^ ((kk_) << 5)));      \
        _Pragma("unroll")                                                       \
        for (int n2 = 0; n2 < 4; n2++)                                          \
            ldsm4(Bh[n2], (boff_) + ((b_swb + n2 * 1024) ^ ((kk_) << 5)));      \
        _Pragma("unroll")                                                       \
        for (int mt = 0; mt < 2; mt++)                                          \
            _Pragma("unroll")                                                   \
            for (int n2 = 0; n2 < 4; n2++) {                                    \
                mma_h(acc[mt][2*n2],   Ah[mt], Bh[n2][0], Bh[n2][1]);           \
                mma_h(acc[mt][2*n2+1], Ah[mt], Bh[n2][2], Bh[n2][3]);           \
            }                                                                   \
    }

// ---------------- GEMM1: act = silu(x@Wg^T)*(x@Wu^T) ----------------
// block 64m x 128 B-rows (64 gate + 64 up -> 64 act cols), BK=32, 4 warps (2m x 2n)
__global__ void __launch_bounds__(128, 4) k_gemm1(const float* __restrict__ w1) {
    const int e = blockIdx.z, cnt = g_cnt[e];
    const int m0 = blockIdx.y * 64;
    if (m0 >= cnt) return;
    const int n0 = blockIdx.x * 64;

    extern __shared__ char sm[];
    const uint32_t sbase = smem_u32(sm);
    __shared__ int s_tok[64];

    const int tid = threadIdx.x, lane = tid & 31, wid = tid >> 5;
    if (tid < 64) { int r = m0 + tid; if (r >= cnt) r = cnt - 1; s_tok[tid] = g_tok[e][r]; }
    __syncthreads();

    // A loader: 2 thr/row, 32B each
    const int lrow = tid >> 1, q = tid & 1;
    const uint32_t* arow = g_x + (size_t)s_tok[lrow] * HW;
    const uint32_t a_sw = (((uint32_t)lrow >> 1) & 3) << 4;
    const uint32_t a_d0 = (uint32_t)lrow * 64 + (((uint32_t)q * 32) ^ a_sw);
    const uint32_t a_d1 = (uint32_t)lrow * 64 + (((uint32_t)q * 32 + 16) ^ a_sw);
    // B loader: 1 thr/row over 128 rows (64 gate + 64 up)
    const int brow = tid;
    const int wrow = (brow < 64) ? (n0 + brow) : (I + n0 + brow - 64);
    const float* bptr = w1 + ((size_t)e * I2 + wrow) * H;
    const uint32_t b_base = (uint32_t)brow * 64;
    const uint32_t b_sw = (((uint32_t)brow >> 1) & 3) << 4;
    // fragment bases
    const int wm = (wid & 1) * 32, wn = (wid >> 1) * 64;
    const uint32_t a_row = wm + (lane & 15);
    const uint32_t a_swb = a_row * 64 +
        ((((uint32_t)lane >> 4) << 4) ^ (((a_row >> 1) & 3) << 4));
    const uint32_t b_row = wn + (lane & 7) + ((lane >> 4) << 3);
    const uint32_t b_swb = b_row * 64 +
        (((((uint32_t)lane >> 3) & 1) << 4) ^ (((b_row >> 1) & 3) << 4));

    float acc[2][8][4] = {};
    float4 bv[4];
    const int KT = H / 32;

    LDG_BH(0, 0);  STS_BH(0, 0);
    LDG_BH(0, 1);  STS_BH(0, 1);
    ISSUE_A(0);
    ISSUE_A(1);

    for (int kt = 0; kt < KT; kt++) {
        if (kt + 1 < KT) LDG_BH(kt + 1, 0);
        CPWAIT(1);
        __syncthreads();
        ISSUE_A(kt + 2);
        const uint32_t aoff = sbase + A_STG(kt);
        const uint32_t boff = sbase + B_BUF(kt & 1);
        COMPUTE_KK(0, aoff, boff);
        if (kt + 1 < KT) { STS_BH((kt + 1) & 1, 0); LDG_BH(kt + 1, 1); }
        COMPUTE_KK(1, aoff, boff);
        if (kt + 1 < KT) STS_BH((kt + 1) & 1, 1);
    }

    // epilogue: stage D [64][132], recombine gate/up, fp16 pack, store act
    CPWAIT(0);
    __syncthreads();
    float* stg = (float*)sm;
    #pragma unroll
    for (int mt = 0; mt < 2; mt++)
        #pragma unroll
        for (int nf = 0; nf < 8; nf++) {
            int r = wm + mt * 16 + (lane >> 2);
            int c = wn + nf * 8 + (lane & 3) * 2;
            stg[r * 132 + c]           = acc[mt][nf][0];
            stg[r * 132 + c + 1]       = acc[mt][nf][1];
            stg[(r + 8) * 132 + c]     = acc[mt][nf][2];
            stg[(r + 8) * 132 + c + 1] = acc[mt][nf][3];
        }
    __syncthreads();
    const int erow = tid >> 1, grow = m0 + erow;
    if (grow < cnt) {
        const int pc = (tid & 1) * 32;   // 32 act cols per thread
        uint32_t hw[16];
        #pragma unroll
        for (int j = 0; j < 16; j++) {
            int c0 = pc + 2 * j;
            float g0 = stg[erow * 132 + c0],      g1 = stg[erow * 132 + c0 + 1];
            float u0 = stg[erow * 132 + 64 + c0], u1 = stg[erow * 132 + 65 + c0];
            float a0 = g0 / (1.f + __expf(-g0)) * u0;
            float a1 = g1 / (1.f + __expf(-g1)) * u1;
            hw[j] = packh(a0, a1);
        }
        size_t base = ((size_t)e * T + grow) * IW + (n0 >> 1) + (pc >> 1);
        #pragma unroll
        for (int p4 = 0; p4 < 4; p4++)
            *(uint4*)(g_act + base + 4 * p4) =
                make_uint4(hw[4*p4], hw[4*p4+1], hw[4*p4+2], hw[4*p4+3]);
    }
}

// ---------------- GEMM2: out[tok] += cw * (act @ W2^T) ----------------
// block 64m x 128n, BK=32, 4 warps (2m x 2n), warp tile 32x64
__global__ void __launch_bounds__(128, 4) k_gemm2(const float* __restrict__ w2,
                                                  float* __restrict__ out) {
    const int e = blockIdx.z, cnt = g_cnt[e];
    const int m0 = blockIdx.y * 64;
    if (m0 >= cnt) return;
    const int n0 = blockIdx.x * 128;

    extern __shared__ char sm[];
    const uint32_t sbase = smem_u32(sm);
    __shared__ int   s_tok[64];
    __shared__ float s_cw [64];

    const int tid = threadIdx.x, lane = tid & 31, wid = tid >> 5;
    if (tid < 64) {
        int r = m0 + tid, rr = (r < cnt) ? r : (cnt - 1);
        s_tok[tid] = g_tok[e][rr];
        s_cw [tid] = (r < cnt) ? g_cw[e][r] : 0.f;
    }
    __syncthreads();

    const int lrow = tid >> 1, q = tid & 1;
    int ar = m0 + lrow; if (ar >= cnt) ar = cnt - 1;
    const uint32_t* arow = g_act + ((size_t)e * T + ar) * IW;
    const uint32_t a_sw = (((uint32_t)lrow >> 1) & 3) << 4;
    const uint32_t a_d0 = (uint32_t)lrow * 64 + (((uint32_t)q * 32) ^ a_sw);
    const uint32_t a_d1 = (uint32_t)lrow * 64 + (((uint32_t)q * 32 + 16) ^ a_sw);
    const int brow = tid;
    const float* bptr = w2 + ((size_t)e * H + n0 + brow) * I;
    const uint32_t b_base = (uint32_t)brow * 64;
    const uint32_t b_sw = (((uint32_t)brow >> 1) & 3) << 4;

    const int wm = (wid & 1) * 32, wn = (wid >> 1) * 64;
    const uint32_t a_row = wm + (lane & 15);
    const uint32_t a_swb = a_row * 64 +
        ((((uint32_t)lane >> 4) << 4) ^ (((a_row >> 1) & 3) << 4));
    const uint32_t b_row = wn + (lane & 7) + ((lane >> 4) << 3);
    const uint32_t b_swb = b_row * 64 +
        (((((uint32_t)lane >> 3) & 1) << 4) ^ (((b_row >> 1) & 3) << 4));

    float acc[2][8][4] = {};
    float4 bv[4];
    const int KT = I / 32;

    LDG_BH(0, 0);  STS_BH(0, 0);
    LDG_BH(0, 1);  STS_BH(0, 1);
    ISSUE_A(0);
    ISSUE_A(1);

    for (int kt = 0; kt < KT; kt++) {
        if (kt + 1 < KT) LDG_BH(kt + 1, 0);
        CPWAIT(1);
        __syncthreads();
        ISSUE_A(kt + 2);
        const uint32_t aoff = sbase + A_STG(kt);
        const uint32_t boff = sbase + B_BUF(kt & 1);
        COMPUTE_KK(0, aoff, boff);
        if (kt + 1 < KT) { STS_BH((kt + 1) & 1, 0); LDG_BH(kt + 1, 1); }
        COMPUTE_KK(1, aoff, boff);
        if (kt + 1 < KT) STS_BH((kt + 1) & 1, 1);
    }
    CPWAIT(0);

    // epilogue: scale + atomicAdd (each out element receives exactly 2 adds total)
    #pragma unroll
    for (int mt = 0; mt < 2; mt++)
        #pragma unroll
        for (int nf = 0; nf < 8; nf++) {
            int r = wm + mt * 16 + (lane >> 2);
            int c = n0 + wn + nf * 8 + (lane & 3) * 2;
            if (m0 + r < cnt) {
                float cw = s_cw[r];
                float* op = out + (size_t)s_tok[r] * H + c;
                atomicAdd(op,     acc[mt][nf][0] * cw);
                atomicAdd(op + 1, acc[mt][nf][1] * cw);
            }
            if (m0 + r + 8 < cnt) {
                float cw = s_cw[r + 8];
                float* op = out + (size_t)s_tok[r + 8] * H + c;
                atomicAdd(op,     acc[mt][nf][2] * cw);
                atomicAdd(op + 1, acc[mt][nf][3] * cw);
            }
        }
}

// ---------------- launch ----------------
extern "C" void kernel_launch(void* const* d_in, const int* in_sizes, int n_in,
                              void* d_out, int out_size) {
    const float* x  = (const float*)d_in[0];   // [T, H]
    const float* w1 = (const float*)d_in[1];   // [E, 2I, H]
    const float* w2 = (const float*)d_in[2];   // [E, H, I]
    const float* wg = (const float*)d_in[3];   // [E, H]
    float* out = (float*)d_out;                // [T, 1, H]

    cudaFuncSetAttribute(k_gemm1, cudaFuncAttributeMaxDynamicSharedMemorySize, SMEM1);
    cudaFuncSetAttribute(k_gemm2, cudaFuncAttributeMaxDynamicSharedMemorySize, SMEM2);

    k_init<<<1, 32>>>();
    k_router<<<T, 256>>>(x, wg, out);
    k_gemm1<<<dim3(I / 64, (T + 63) / 64, E), 128, SMEM1>>>(w1);
    k_gemm2<<<dim3(H / 128, (T + 63) / 64, E), 128, SMEM2>>>(w2, out);
}

// round 11
// speedup vs baseline: 1.9737x; 1.9737x over previous
#include <cuda_runtime.h>
#include <cuda_fp16.h>
#include <cstdint>

#define H   2048
#define I   1408
#define E   8
#define T   512
#define I2  2816   // 2*I
#define IW  704    // I/2: act row width in uint32 (fp16 pairs)
#define HW  1024   // H/2: x row width in uint32 (fp16 pairs)

// gemm1 smem: A fp16 ring 3x8KB @0, B fp16 double 2x8KB @0x6000; epi stage 128*68*4=34816
#define SMEM1    0xA000   // 40 KB
// gemm2 smem: A fp16 ring 3x4KB @0, B fp16 double 2x8KB @0x3000
#define SMEM2    0x7000   // 28 KB

// ---------------- device scratch (no allocations allowed) ----------------
__device__ int   g_cnt[E];
__device__ int   g_tok[E][T];
__device__ float g_cw [E][T];
__device__ __align__(16) uint32_t g_act[(size_t)E * T * IW];  // fp16 pairs
__device__ __align__(16) uint32_t g_x  [(size_t)T * HW];      // fp16 pairs

// ---------------- helpers ----------------
__device__ __forceinline__ uint32_t smem_u32(const void* p) {
    uint32_t a;
    asm("{ .reg .u64 t; cvta.to.shared.u64 t, %1; cvt.u32.u64 %0, t; }" : "=r"(a) : "l"(p));
    return a;
}
// pack two fp32 -> fp16x2 (first arg in low 16 bits)
__device__ __forceinline__ uint32_t packh(float lo, float hi) {
    uint32_t r;
    asm("cvt.rn.f16x2.f32 %0, %1, %2;" : "=r"(r) : "f"(hi), "f"(lo));
    return r;
}
__device__ __forceinline__ void ldsm4(uint32_t* r, uint32_t a) {
    asm volatile("ldmatrix.sync.aligned.m8n8.x4.shared.b16 {%0,%1,%2,%3}, [%4];"
        : "=r"(r[0]), "=r"(r[1]), "=r"(r[2]), "=r"(r[3]) : "r"(a));
}
__device__ __forceinline__ void mma_h(float* d, const uint32_t* a, uint32_t b0, uint32_t b1) {
    asm volatile("mma.sync.aligned.m16n8k16.row.col.f32.f16.f16.f32 "
        "{%0,%1,%2,%3}, {%4,%5,%6,%7}, {%8,%9}, {%0,%1,%2,%3};"
        : "+f"(d[0]), "+f"(d[1]), "+f"(d[2]), "+f"(d[3])
        : "r"(a[0]), "r"(a[1]), "r"(a[2]), "r"(a[3]), "r"(b0), "r"(b1));
}
#define CP16(d_, s_)  asm volatile("cp.async.cg.shared.global [%0], [%1], 16;" :: "r"(d_), "l"(s_))
#define CPCOMMIT()    asm volatile("cp.async.commit_group;" ::)
#define CPWAIT(n_)    asm volatile("cp.async.wait_group %0;" :: "n"(n_))

// ---------------- init ----------------
__global__ void k_init() {
    if (threadIdx.x < E) g_cnt[threadIdx.x] = 0;
}

// ---------------- router: zero out row, convert x row to fp16, route ----------------
__global__ void k_router(const float* __restrict__ x, const float* __restrict__ wg,
                         float* __restrict__ out) {
    const int t = blockIdx.x, tid = threadIdx.x, w = tid >> 5, lane = tid & 31;
    const float* xr = x + (size_t)t * H;
    float4 z = make_float4(0.f, 0.f, 0.f, 0.f);
    *(float4*)(out + (size_t)t * H + tid * 4)        = z;
    *(float4*)(out + (size_t)t * H + 1024 + tid * 4) = z;
    #pragma unroll
    for (int i = tid * 4; i < H; i += 1024) {
        float4 v = *(const float4*)(xr + i);
        *(uint2*)(g_x + (size_t)t * HW + i / 2) =
            make_uint2(packh(v.x, v.y), packh(v.z, v.w));
    }
    const float* gr = wg + (size_t)w * H;
    float s = 0.f;
    for (int i = lane * 4; i < H; i += 128) {
        float4 xv = *(const float4*)(xr + i);
        float4 gv = *(const float4*)(gr + i);
        s += xv.x * gv.x + xv.y * gv.y + xv.z * gv.z + xv.w * gv.w;
    }
    #pragma unroll
    for (int o = 16; o; o >>= 1) s += __shfl_xor_sync(0xffffffffu, s, o);
    __shared__ float lg[E];
    if (lane == 0) lg[w] = s;
    __syncthreads();
    if (tid == 0) {
        float mx = lg[0];
        #pragma unroll
        for (int e = 1; e < E; e++) mx = fmaxf(mx, lg[e]);
        float ex[E];
        #pragma unroll
        for (int e = 0; e < E; e++) ex[e] = expf(lg[e] - mx);
        int i0 = 0;
        #pragma unroll
        for (int e = 1; e < E; e++) if (ex[e] > ex[i0]) i0 = e;
        int i1 = (i0 == 0) ? 1 : 0;
        #pragma unroll
        for (int e = 0; e < E; e++) if (e != i0 && ex[e] > ex[i1]) i1 = e;
        float s0 = ex[i0], s1 = ex[i1], inv = 1.f / (s0 + s1);
        int p0 = atomicAdd(&g_cnt[i0], 1);
        g_tok[i0][p0] = t;  g_cw[i0][p0] = s0 * inv;
        int p1 = atomicAdd(&g_cnt[i1], 1);
        g_tok[i1][p1] = t;  g_cw[i1][p1] = s1 * inv;
    }
}

// B prefetch: 16 floats per thread (2 thr/row over 128 rows)
#define LDG_B(kt_)                                                              \
    { const float* p = bptr + (size_t)(kt_) * 32;                               \
      bv[0] = *(const float4*)p;       bv[1] = *(const float4*)(p + 4);         \
      bv[2] = *(const float4*)(p + 8); bv[3] = *(const float4*)(p + 12); }

// convert 16 fp32 -> 16 fp16, store two 16B chunks into 64B-row B tile
#define STS_B(boff_)                                                            \
    { char* s = sm + (boff_);                                                   \
      uint32_t u[8];                                                            \
      _Pragma("unroll")                                                         \
      for (int i = 0; i < 4; i++) {                                             \
          u[2*i]   = packh(bv[i].x, bv[i].y);                                   \
          u[2*i+1] = packh(bv[i].z, bv[i].w);                                   \
      }                                                                         \
      *(uint4*)(s + b_sts0)        = make_uint4(u[0], u[1], u[2], u[3]);        \
      *(uint4*)(s + (b_sts0 ^ 16)) = make_uint4(u[4], u[5], u[6], u[7]);        \
    }

// ---------------- GEMM1: act = silu(x@Wg^T)*(x@Wu^T) ----------------
// block 128m x 128 B-rows, gate/up interleaved (even row=gate, odd=up -> 64 act cols)
// BK=32, 8 warps (2m x 4n), warp tile 64m x 32n
__global__ void __launch_bounds__(256, 2) k_gemm1(const float* __restrict__ w1) {
    const int e = blockIdx.z, cnt = g_cnt[e];
    const int m0 = blockIdx.y * 128;
    if (m0 >= cnt) return;
    const int n0 = blockIdx.x * 64;   // act col base

    extern __shared__ char sm[];
    const uint32_t sbase = smem_u32(sm);
    __shared__ int s_tok[128];

    const int tid = threadIdx.x, lane = tid & 31, wid = tid >> 5;
    if (tid < 128) { int r = m0 + tid; if (r >= cnt) r = cnt - 1; s_tok[tid] = g_tok[e][r]; }
    __syncthreads();

    // A loader: 2 thr/row over 128 rows, 32B each (two 16B chunks)
    const int lrow = tid >> 1, q = tid & 1;
    const uint32_t* arow = g_x + (size_t)s_tok[lrow] * HW;
    const uint32_t a_sw = (((uint32_t)lrow >> 1) & 3) << 4;
    const uint32_t a_d0 = (uint32_t)lrow * 64 + (((uint32_t)q * 32) ^ a_sw);
    const uint32_t a_d1 = (uint32_t)lrow * 64 + (((uint32_t)q * 32 + 16) ^ a_sw);
    // B loader: 2 thr/row over 128 interleaved rows (even=gate, odd=up)
    const int brow = tid >> 1, bh = tid & 1;
    const int wrow = (brow & 1) ? (I + n0 + (brow >> 1)) : (n0 + (brow >> 1));
    const float* bptr = w1 + ((size_t)e * I2 + wrow) * H + bh * 16;
    const uint32_t b_sts0 = (uint32_t)brow * 64 +
        (((uint32_t)bh << 5) ^ ((((uint32_t)brow >> 1) & 3) << 4));
    // fragment bases
    const int wm = (wid & 1) * 64, wn = (wid >> 1) * 32;
    const uint32_t a_row = wm + (lane & 15);
    const uint32_t a_swb = a_row * 64 +
        ((((uint32_t)lane >> 4) << 4) ^ (((a_row >> 1) & 3) << 4));
    const uint32_t b_row = wn + (lane & 7) + ((lane >> 4) << 3);
    const uint32_t b_swb = b_row * 64 +
        (((((uint32_t)lane >> 3) & 1) << 4) ^ (((b_row >> 1) & 3) << 4));

    float acc[4][4][4] = {};
    float4 bv[4];
    const int KT = H / 32;

    // A cp.async stage issue (8KB stages @ <<13)
    #define ISSUE_A1(kt_)                                                       \
        do {                                                                    \
            if ((kt_) < KT) {                                                   \
                uint32_t st = sbase + (((kt_) % 3) << 13);                      \
                const uint32_t* s = arow + (kt_) * 16 + q * 8;                  \
                CP16(st + a_d0, (const char*)s);                                \
                CP16(st + a_d1, (const char*)(s + 4));                          \
            }                                                                   \
            CPCOMMIT();                                                         \
        } while (0)

    ISSUE_A1(0);
    ISSUE_A1(1);
    LDG_B(0);
    STS_B(0x6000);

    for (int kt = 0; kt < KT; kt++) {
        if (kt + 1 < KT) LDG_B(kt + 1);
        CPWAIT(1);
        __syncthreads();
        ISSUE_A1(kt + 2);
        const uint32_t aoff = sbase + ((kt % 3) << 13);
        const uint32_t boff = sbase + 0x6000 + ((kt & 1) << 13);
        #pragma unroll
        for (int kk = 0; kk < 2; kk++) {
            uint32_t Ah[4][4], Bh[2][4];
            #pragma unroll
            for (int mt = 0; mt < 4; mt++)
                ldsm4(Ah[mt], aoff + ((a_swb + mt * 1024) ^ (kk << 5)));
            #pragma unroll
            for (int n2 = 0; n2 < 2; n2++)
                ldsm4(Bh[n2], boff + ((b_swb + n2 * 1024) ^ (kk << 5)));
            #pragma unroll
            for (int mt = 0; mt < 4; mt++)
                #pragma unroll
                for (int n2 = 0; n2 < 2; n2++) {
                    mma_h(acc[mt][2*n2],   Ah[mt], Bh[n2][0], Bh[n2][1]);
                    mma_h(acc[mt][2*n2+1], Ah[mt], Bh[n2][2], Bh[n2][3]);
                }
        }
        if (kt + 1 < KT) STS_B(0x6000 + (((kt + 1) & 1) << 13));
    }

    // epilogue: gate/up pairs are adjacent in acc -> act in-register, stage [128][68] fp32
    CPWAIT(0);
    __syncthreads();
    float* stg = (float*)sm;
    #pragma unroll
    for (int mt = 0; mt < 4; mt++)
        #pragma unroll
        for (int nf = 0; nf < 4; nf++) {
            int r = wm + mt * 16 + (lane >> 2);
            int a = (wn >> 1) + nf * 4 + (lane & 3);
            float g0 = acc[mt][nf][0], u0 = acc[mt][nf][1];
            float g1 = acc[mt][nf][2], u1 = acc[mt][nf][3];
            stg[r * 68 + a]       = g0 / (1.f + __expf(-g0)) * u0;
            stg[(r + 8) * 68 + a] = g1 / (1.f + __expf(-g1)) * u1;
        }
    __syncthreads();
    const int erow = tid >> 1, grow = m0 + erow;
    if (grow < cnt) {
        const int pc = (tid & 1) * 32;   // 32 act cols per thread
        uint32_t hw[16];
        #pragma unroll
        for (int j = 0; j < 16; j++) {
            int c0 = pc + 2 * j;
            hw[j] = packh(stg[erow * 68 + c0], stg[erow * 68 + c0 + 1]);
        }
        size_t base = ((size_t)e * T + grow) * IW + (n0 >> 1) + (pc >> 1);
        #pragma unroll
        for (int p4 = 0; p4 < 4; p4++)
            *(uint4*)(g_act + base + 4 * p4) =
                make_uint4(hw[4*p4], hw[4*p4+1], hw[4*p4+2], hw[4*p4+3]);
    }
    #undef ISSUE_A1
}

// ---------------- GEMM2: out[tok] += cw * (act @ W2^T) ----------------
// block 64m x 128n, BK=32, 8 warps (2m x 4n), warp tile 32x32  (R9 proven)
__global__ void __launch_bounds__(256, 2) k_gemm2(const float* __restrict__ w2,
                                                  float* __restrict__ out) {
    const int e = blockIdx.z, cnt = g_cnt[e];
    const int m0 = blockIdx.y * 64;
    if (m0 >= cnt) return;
    const int n0 = blockIdx.x * 128;

    extern __shared__ char sm[];
    const uint32_t sbase = smem_u32(sm);
    __shared__ int   s_tok[64];
    __shared__ float s_cw [64];

    const int tid = threadIdx.x, lane = tid & 31, wid = tid >> 5;
    if (tid < 64) {
        int r = m0 + tid, rr = (r < cnt) ? r : (cnt - 1);
        s_tok[tid] = g_tok[e][rr];
        s_cw [tid] = (r < cnt) ? g_cw[e][r] : 0.f;
    }
    __syncthreads();

    // A loader: 4 thr/row over 64 rows, 16B each
    const int lrow = tid >> 2, q = tid & 3;
    int ar = m0 + lrow; if (ar >= cnt) ar = cnt - 1;
    const uint32_t* arow = g_act + ((size_t)e * T + ar) * IW;
    const uint32_t a_dst0 = (uint32_t)lrow * 64 +
        (((uint32_t)q * 16) ^ ((((uint32_t)lrow >> 1) & 3) << 4));
    const int brow = tid >> 1, bh = tid & 1;
    const float* bptr = w2 + ((size_t)e * H + n0 + brow) * I + bh * 16;
    const uint32_t b_sts0 = (uint32_t)brow * 64 +
        (((uint32_t)bh << 5) ^ ((((uint32_t)brow >> 1) & 3) << 4));

    const int wm = (wid & 1) * 32, wn = (wid >> 1) * 32;
    const uint32_t a_row = wm + (lane & 15);
    const uint32_t a_swb = a_row * 64 +
        ((((uint32_t)lane >> 4) << 4) ^ (((a_row >> 1) & 3) << 4));
    const uint32_t b_row = wn + (lane & 7) + ((lane >> 4) << 3);
    const uint32_t b_swb = b_row * 64 +
        (((((uint32_t)lane >> 3) & 1) << 4) ^ (((b_row >> 1) & 3) << 4));

    float acc[2][4][4] = {};
    float4 bv[4];
    const int KT = I / 32;

    #define ISSUE_A2(kt_)                                                       \
        do {                                                                    \
            if ((kt_) < KT) {                                                   \
                uint32_t da = sbase + (((kt_) % 3) << 12) + a_dst0;             \
                CP16(da, (const char*)(arow + (kt_) * 16 + q * 4));             \
            }                                                                   \
            CPCOMMIT();                                                         \
        } while (0)

    ISSUE_A2(0);
    ISSUE_A2(1);
    LDG_B(0);
    STS_B(0x3000);

    for (int kt = 0; kt < KT; kt++) {
        if (kt + 1 < KT) LDG_B(kt + 1);
        CPWAIT(1);
        __syncthreads();
        ISSUE_A2(kt + 2);
        const uint32_t aoff = sbase + ((kt % 3) << 12);
        const uint32_t boff = sbase + 0x3000 + ((kt & 1) << 13);
        #pragma unroll
        for (int kk = 0; kk < 2; kk++) {
            uint32_t Ah[2][4], Bh[2][4];
            #pragma unroll
            for (int mt = 0; mt < 2; mt++)
                ldsm4(Ah[mt], aoff + ((a_swb + mt * 1024) ^ (kk << 5)));
            #pragma unroll
            for (int n2 = 0; n2 < 2; n2++)
                ldsm4(Bh[n2], boff + ((b_swb + n2 * 1024) ^ (kk << 5)));
            #pragma unroll
            for (int mt = 0; mt < 2; mt++)
                #pragma unroll
                for (int n2 = 0; n2 < 2; n2++) {
                    mma_h(acc[mt][2*n2],   Ah[mt], Bh[n2][0], Bh[n2][1]);
                    mma_h(acc[mt][2*n2+1], Ah[mt], Bh[n2][2], Bh[n2][3]);
                }
        }
        if (kt + 1 < KT) STS_B(0x3000 + (((kt + 1) & 1) << 13));
    }
    CPWAIT(0);

    // epilogue: scale + atomicAdd (each out element receives exactly 2 adds total)
    #pragma unroll
    for (int mt = 0; mt < 2; mt++)
        #pragma unroll
        for (int f = 0; f < 4; f++) {
            int r = wm + mt * 16 + (lane >> 2);
            int c = n0 + wn + f * 8 + (lane & 3) * 2;
            if (m0 + r < cnt) {
                float cw = s_cw[r];
                float* op = out + (size_t)s_tok[r] * H + c;
                atomicAdd(op,     acc[mt][f][0] * cw);
                atomicAdd(op + 1, acc[mt][f][1] * cw);
            }
            if (m0 + r + 8 < cnt) {
                float cw = s_cw[r + 8];
                float* op = out + (size_t)s_tok[r + 8] * H + c;
                atomicAdd(op,     acc[mt][f][2] * cw);
                atomicAdd(op + 1, acc[mt][f][3] * cw);
            }
        }
    #undef ISSUE_A2
}

// ---------------- launch ----------------
extern "C" void kernel_launch(void* const* d_in, const int* in_sizes, int n_in,
                              void* d_out, int out_size) {
    const float* x  = (const float*)d_in[0];   // [T, H]
    const float* w1 = (const float*)d_in[1];   // [E, 2I, H]
    const float* w2 = (const float*)d_in[2];   // [E, H, I]
    const float* wg = (const float*)d_in[3];   // [E, H]
    float* out = (float*)d_out;                // [T, 1, H]

    cudaFuncSetAttribute(k_gemm1, cudaFuncAttributeMaxDynamicSharedMemorySize, SMEM1);
    cudaFuncSetAttribute(k_gemm2, cudaFuncAttributeMaxDynamicSharedMemorySize, SMEM2);

    k_init<<<1, 32>>>();
    k_router<<<T, 256>>>(x, wg, out);
    k_gemm1<<<dim3(I / 64, (T + 127) / 128, E), 256, SMEM1>>>(w1);
    k_gemm2<<<dim3(H / 128, (T + 63) / 64, E), 256, SMEM2>>>(w2, out);
}